// round 8
// baseline (speedup 1.0000x reference)
#include <cuda_runtime.h>
#include <cuda_bf16.h>

// SmoothnessLoss: loss = mean_i( (sHat_i - sY_i)^2 ), i in [0, W), W = N-k-1
// s_i = sum_{j<k} | x[i+j] - mean_j |, k = 64.
// Persistent kernel, WPT=8. COMPACT-CODE version: hot math in small unroll-1
// loops (I$-resident) instead of ~36KB of straight-line unrolled code.

#define K_WIN 64
#define BLOCK 256
#define WPT 8
#define STRIDE (BLOCK * WPT)                 // 2048 windows per block-iteration
#define GRID 296                             // 2 blocks/SM x 148 SMs

typedef unsigned long long u64;

__device__ float g_partials[GRID];
__device__ unsigned int g_count = 0;

__device__ __forceinline__ u64 addx2(u64 a, u64 b) {
    u64 r; asm("add.rn.f32x2 %0, %1, %2;" : "=l"(r) : "l"(a), "l"(b)); return r;
}
__device__ __forceinline__ u64 pk(float lo, float hi) {
    u64 r; asm("mov.b64 %0, {%1, %2};" : "=l"(r) : "f"(lo), "f"(hi)); return r;
}
__device__ __forceinline__ void upk(u64 p, float& lo, float& hi) {
    asm("mov.b64 {%0, %1}, %2;" : "=f"(lo), "=f"(hi) : "l"(p));
}
__device__ __forceinline__ u64 absx2(u64 a) { return a & 0x7FFFFFFF7FFFFFFFULL; }
__device__ __forceinline__ float sum2(u64 a) { float l, h; upk(a, l, h); return l + h; }

// Opaque 16B load (prevents CSE with pass-1 values; L1 hit expected).
__device__ __forceinline__ void ldg2(const ulonglong2* p, u64& x, u64& y) {
    asm volatile("ld.global.nc.v2.u64 {%0, %1}, [%2];"
                 : "=l"(x), "=l"(y) : "l"(p));
}

// 8 windows over a fully in-bounds 72-float segment (16B-aligned).
// Pairs P_j = elements {2j, 2j+1}; chunk q (ulonglong2) = pairs {2q, 2q+1}.
__device__ __forceinline__ void seg8(const float* __restrict__ p, float a[WPT])
{
    const ulonglong2* p2 = reinterpret_cast<const ulonglong2*>(p);

    // Boundary chunks (kept in registers).
    ulonglong2 k0 = p2[0], k1 = p2[1];           // pairs 0..3   (elements 0..7)
    ulonglong2 k16 = p2[16], k17 = p2[17];       // pairs 32..35 (elements 64..71)

    // ---- Pass 1: sum of elements [0,64): compact loop, 4 chains ----
    u64 t0 = k0.x, t1 = k0.y, t2 = k1.x, t3 = k1.y;
    #pragma unroll 1
    for (int c = 2; c < 16; c += 2) {
        ulonglong2 ca = p2[c], cb = p2[c + 1];
        t0 = addx2(t0, ca.x);
        t1 = addx2(t1, ca.y);
        t2 = addx2(t2, cb.x);
        t3 = addx2(t3, cb.y);
    }
    float lo, hi; upk(addx2(addx2(t0, t1), addx2(t2, t3)), lo, hi);

    float e[8], f[8];
    upk(k0.x,  e[0], e[1]); upk(k0.y,  e[2], e[3]);
    upk(k1.x,  e[4], e[5]); upk(k1.y,  e[6], e[7]);
    upk(k16.x, f[0], f[1]); upk(k16.y, f[2], f[3]);
    upk(k17.x, f[4], f[5]); upk(k17.y, f[6], f[7]);

    const float invk = 1.0f / (float)K_WIN;
    float s = lo + hi;
    float m[WPT]; u64 nm[WPT];
    #pragma unroll
    for (int w = 0; w < WPT; w++) {
        m[w]  = s * invk;
        nm[w] = pk(-m[w], -m[w]);
        s += f[w] - e[w];
    }

    // ---- Pass 2: abs-deviation sums. Interior chunks in a compact loop. ----
    u64 A[WPT], B[WPT];
    #pragma unroll
    for (int w = 0; w < WPT; w++) { A[w] = 0ULL; B[w] = 0ULL; }

    #pragma unroll 1
    for (int c = 2; c < 16; c++) {               // pairs 4..31: in all 8 windows
        u64 cx, cy;
        ldg2(p2 + c, cx, cy);
        #pragma unroll
        for (int w = 0; w < WPT; w++) {
            A[w] = addx2(A[w], absx2(addx2(cx, nm[w])));
            B[w] = addx2(B[w], absx2(addx2(cy, nm[w])));
        }
    }

    // Boundary pairs (registers from above).
    const u64 P0 = k0.x,  P1 = k0.y,  P2 = k1.x,  P3 = k1.y;
    const u64 P32 = k16.x, P33 = k16.y, P34 = k17.x;

    // Even windows w=2a: full pairs a..a+31 -> extras beyond interior 4..31.
    A[0] = addx2(A[0], absx2(addx2(P0,  nm[0])));
    B[0] = addx2(B[0], absx2(addx2(P1,  nm[0])));
    A[0] = addx2(A[0], absx2(addx2(P2,  nm[0])));
    B[0] = addx2(B[0], absx2(addx2(P3,  nm[0])));

    A[2] = addx2(A[2], absx2(addx2(P1,  nm[2])));
    B[2] = addx2(B[2], absx2(addx2(P2,  nm[2])));
    A[2] = addx2(A[2], absx2(addx2(P3,  nm[2])));
    B[2] = addx2(B[2], absx2(addx2(P32, nm[2])));

    A[4] = addx2(A[4], absx2(addx2(P2,  nm[4])));
    B[4] = addx2(B[4], absx2(addx2(P3,  nm[4])));
    A[4] = addx2(A[4], absx2(addx2(P32, nm[4])));
    B[4] = addx2(B[4], absx2(addx2(P33, nm[4])));

    A[6] = addx2(A[6], absx2(addx2(P3,  nm[6])));
    B[6] = addx2(B[6], absx2(addx2(P32, nm[6])));
    A[6] = addx2(A[6], absx2(addx2(P33, nm[6])));
    B[6] = addx2(B[6], absx2(addx2(P34, nm[6])));

    // Odd windows w=2a+1: full pairs a+1..a+31 + scalar ends e[w], f[w-1].
    A[1] = addx2(A[1], absx2(addx2(P1,  nm[1])));
    B[1] = addx2(B[1], absx2(addx2(P2,  nm[1])));
    A[1] = addx2(A[1], absx2(addx2(P3,  nm[1])));

    A[3] = addx2(A[3], absx2(addx2(P2,  nm[3])));
    B[3] = addx2(B[3], absx2(addx2(P3,  nm[3])));
    A[3] = addx2(A[3], absx2(addx2(P32, nm[3])));

    A[5] = addx2(A[5], absx2(addx2(P3,  nm[5])));
    B[5] = addx2(B[5], absx2(addx2(P32, nm[5])));
    A[5] = addx2(A[5], absx2(addx2(P33, nm[5])));

    A[7] = addx2(A[7], absx2(addx2(P32, nm[7])));
    B[7] = addx2(B[7], absx2(addx2(P33, nm[7])));
    A[7] = addx2(A[7], absx2(addx2(P34, nm[7])));

    const float ex1 = fabsf(e[1] - m[1]) + fabsf(f[0] - m[1]);
    const float ex3 = fabsf(e[3] - m[3]) + fabsf(f[2] - m[3]);
    const float ex5 = fabsf(e[5] - m[5]) + fabsf(f[4] - m[5]);
    const float ex7 = fabsf(e[7] - m[7]) + fabsf(f[6] - m[7]);

    a[0] = sum2(addx2(A[0], B[0]));
    a[1] = sum2(addx2(A[1], B[1])) + ex1;
    a[2] = sum2(addx2(A[2], B[2]));
    a[3] = sum2(addx2(A[3], B[3])) + ex3;
    a[4] = sum2(addx2(A[4], B[4]));
    a[5] = sum2(addx2(A[5], B[5])) + ex5;
    a[6] = sum2(addx2(A[6], B[6]));
    a[7] = sum2(addx2(A[7], B[7])) + ex7;
}

// Rare tail fallback (segment not fully in-bounds). Compact loops.
__device__ void seg8_scalar(const float* __restrict__ p, int rem, float a[WPT])
{
    #pragma unroll 1
    for (int w = 0; w < WPT; w++) {
        float s = 0.0f;
        #pragma unroll 1
        for (int j = 0; j < K_WIN; j++) {
            const int idx = w + j;
            s += (idx < rem) ? p[idx] : 0.0f;
        }
        const float m = s * (1.0f / (float)K_WIN);
        float t = 0.0f;
        #pragma unroll 1
        for (int j = 0; j < K_WIN; j++) {
            const int idx = w + j;
            const float x = (idx < rem) ? p[idx] : 0.0f;
            t += fabsf(x - m);
        }
        a[w] = t;
    }
}

__global__ void __launch_bounds__(BLOCK, 2)
smoothness_persist_kernel(const float* __restrict__ yh,
                          const float* __restrict__ yy,
                          int W, int N, int WB,
                          float* __restrict__ out, double invW)
{
    __shared__ float  redf[BLOCK / 32];
    __shared__ double redd[BLOCK / 32];
    __shared__ int    amLast;

    const int tid    = threadIdx.x;
    const int wstart = blockIdx.x * WB;            // multiple of 8
    const int wend   = min(wstart + WB, W);

    float d2 = 0.0f;

    #pragma unroll 1
    for (int i0 = wstart + WPT * tid; i0 < wend; i0 += STRIDE) {
        float a1[WPT], a2[WPT];
        if (N - i0 >= 8 * WPT + 8) {               // 72 elements fully in-bounds
            seg8(yh + i0, a1);
            seg8(yy + i0, a2);
        } else {
            seg8_scalar(yh + i0, N - i0, a1);
            seg8_scalar(yy + i0, N - i0, a2);
        }
        if (i0 + WPT <= wend) {
            #pragma unroll
            for (int w = 0; w < WPT; w++) {
                const float d = a1[w] - a2[w];
                d2 += d * d;
            }
        } else {
            #pragma unroll
            for (int w = 0; w < WPT; w++) {
                if (i0 + w < wend) {
                    const float d = a1[w] - a2[w];
                    d2 += d * d;
                }
            }
        }
    }

    // Block reduction of d2.
    #pragma unroll
    for (int off = 16; off > 0; off >>= 1)
        d2 += __shfl_down_sync(0xffffffffu, d2, off);

    const int lane = tid & 31, wid = tid >> 5;
    if (lane == 0) redf[wid] = d2;
    __syncthreads();
    if (wid == 0) {
        float vv = (lane < BLOCK / 32) ? redf[lane] : 0.0f;
        #pragma unroll
        for (int off = 4; off > 0; off >>= 1)
            vv += __shfl_down_sync(0xffffffffu, vv, off);
        if (lane == 0) {
            g_partials[blockIdx.x] = vv;
            __threadfence();
            unsigned int c = atomicAdd(&g_count, 1u);
            amLast = (c == (unsigned int)(gridDim.x - 1));
        }
    }
    __syncthreads();

    if (amLast) {
        // Deterministic final reduction (fixed order/topology).
        double s = 0.0;
        #pragma unroll 1
        for (int i = tid; i < GRID; i += BLOCK)
            s += (double)g_partials[i];
        #pragma unroll
        for (int off = 16; off > 0; off >>= 1)
            s += __shfl_down_sync(0xffffffffu, s, off);
        if (lane == 0) redd[wid] = s;
        __syncthreads();
        if (wid == 0) {
            double vv = (lane < BLOCK / 32) ? redd[lane] : 0.0;
            #pragma unroll
            for (int off = 4; off > 0; off >>= 1)
                vv += __shfl_down_sync(0xffffffffu, vv, off);
            if (lane == 0) {
                out[0] = (float)(vv * invW);
                g_count = 0;                 // reset for next graph replay
            }
        }
    }
}

extern "C" void kernel_launch(void* const* d_in, const int* in_sizes, int n_in,
                              void* d_out, int out_size)
{
    const float* yh = (const float*)d_in[0];
    const float* yy = (const float*)d_in[1];
    const int N = in_sizes[0];
    const int W = N - K_WIN - 1;
    int WB = (W + GRID - 1) / GRID;
    WB = (WB + 7) & ~7;                          // multiple of 8 (alignment + WPT)

    smoothness_persist_kernel<<<GRID, BLOCK>>>(yh, yy, W, N, WB,
                                               (float*)d_out, 1.0 / (double)W);
}

// round 9
// speedup vs baseline: 1.0992x; 1.0992x over previous
#include <cuda_runtime.h>
#include <cuda_bf16.h>

// SmoothnessLoss: loss = mean_i( (sHat_i - sY_i)^2 ), i in [0, W), W = N-k-1
// s_i = sum_{j<k} | x[i+j] - mean_j |, k = 64.
// Persistent kernel, WPT=8. Pass-1 loads batched (MLP=14); pass-2 volatile
// loads software-pipelined 2-deep so L1 latency is covered by compute.

#define K_WIN 64
#define BLOCK 256
#define WPT 8
#define STRIDE (BLOCK * WPT)                 // 2048 windows per block-iteration
#define GRID 296                             // 2 blocks/SM x 148 SMs

typedef unsigned long long u64;

__device__ float g_partials[GRID];
__device__ unsigned int g_count = 0;

__device__ __forceinline__ u64 addx2(u64 a, u64 b) {
    u64 r; asm("add.rn.f32x2 %0, %1, %2;" : "=l"(r) : "l"(a), "l"(b)); return r;
}
__device__ __forceinline__ u64 pk(float lo, float hi) {
    u64 r; asm("mov.b64 %0, {%1, %2};" : "=l"(r) : "f"(lo), "f"(hi)); return r;
}
__device__ __forceinline__ void upk(u64 p, float& lo, float& hi) {
    asm("mov.b64 {%0, %1}, %2;" : "=f"(lo), "=f"(hi) : "l"(p));
}
__device__ __forceinline__ u64 absx2(u64 a) { return a & 0x7FFFFFFF7FFFFFFFULL; }
__device__ __forceinline__ float sum2(u64 a) { float l, h; upk(a, l, h); return l + h; }

// Opaque 16B load (prevents cross-pass CSE; placement fixed by program order).
__device__ __forceinline__ void ldg2(const ulonglong2* p, u64& x, u64& y) {
    asm volatile("ld.global.nc.v2.u64 {%0, %1}, [%2];"
                 : "=l"(x), "=l"(y) : "l"(p));
}

// 8 windows over a fully in-bounds 72-float segment (16B-aligned).
// Pairs P_j = elements {2j, 2j+1}; chunk q (ulonglong2) = pairs {2q, 2q+1}.
__device__ __forceinline__ void seg8(const float* __restrict__ p, float a[WPT])
{
    const ulonglong2* p2 = reinterpret_cast<const ulonglong2*>(p);

    // Boundary chunks (kept live in registers through pass 2).
    ulonglong2 k0 = p2[0], k1 = p2[1];           // pairs 0..3   (elements 0..7)
    ulonglong2 k16 = p2[16], k17 = p2[17];       // pairs 32..35 (elements 64..71)

    // ---- Pass 1: batch-load interior chunks 2..15 (MLP=14), then add tree ----
    u64 cc[28];
    #pragma unroll
    for (int c = 0; c < 14; c++)
        ldg2(p2 + 2 + c, cc[2 * c], cc[2 * c + 1]);

    u64 t0 = k0.x, t1 = k0.y, t2 = k1.x, t3 = k1.y;
    #pragma unroll
    for (int j = 0; j < 7; j++) {
        t0 = addx2(t0, cc[4 * j]);
        t1 = addx2(t1, cc[4 * j + 1]);
        t2 = addx2(t2, cc[4 * j + 2]);
        t3 = addx2(t3, cc[4 * j + 3]);
    }
    float lo, hi; upk(addx2(addx2(t0, t1), addx2(t2, t3)), lo, hi);

    float e[8], f[8];
    upk(k0.x,  e[0], e[1]); upk(k0.y,  e[2], e[3]);
    upk(k1.x,  e[4], e[5]); upk(k1.y,  e[6], e[7]);
    upk(k16.x, f[0], f[1]); upk(k16.y, f[2], f[3]);
    upk(k17.x, f[4], f[5]); upk(k17.y, f[6], f[7]);

    const float invk = 1.0f / (float)K_WIN;
    float s = lo + hi;
    float m[WPT]; u64 nm[WPT];
    #pragma unroll
    for (int w = 0; w < WPT; w++) {
        m[w]  = s * invk;
        nm[w] = pk(-m[w], -m[w]);
        s += f[w] - e[w];
    }

    // ---- Pass 2: abs-deviation sums; loads pipelined 2 chunks ahead ----
    u64 A[WPT], B[WPT];
    #pragma unroll
    for (int w = 0; w < WPT; w++) { A[w] = 0ULL; B[w] = 0ULL; }

    u64 cx0, cy0, cx1, cy1;
    ldg2(p2 + 2, cx0, cy0);
    ldg2(p2 + 3, cx1, cy1);
    #pragma unroll
    for (int c = 2; c < 16; c++) {               // pairs 4..31: in all 8 windows
        u64 nx = 0ULL, ny = 0ULL;
        if (c + 2 < 16) ldg2(p2 + c + 2, nx, ny);
        #pragma unroll
        for (int w = 0; w < WPT; w++) {
            A[w] = addx2(A[w], absx2(addx2(cx0, nm[w])));
            B[w] = addx2(B[w], absx2(addx2(cy0, nm[w])));
        }
        cx0 = cx1; cy0 = cy1; cx1 = nx; cy1 = ny;
    }

    // Boundary pairs (registers from above).
    const u64 P0 = k0.x,  P1 = k0.y,  P2 = k1.x,  P3 = k1.y;
    const u64 P32 = k16.x, P33 = k16.y, P34 = k17.x;

    // Even windows w=2a: full pairs a..a+31 -> extras beyond interior 4..31.
    A[0] = addx2(A[0], absx2(addx2(P0,  nm[0])));
    B[0] = addx2(B[0], absx2(addx2(P1,  nm[0])));
    A[0] = addx2(A[0], absx2(addx2(P2,  nm[0])));
    B[0] = addx2(B[0], absx2(addx2(P3,  nm[0])));

    A[2] = addx2(A[2], absx2(addx2(P1,  nm[2])));
    B[2] = addx2(B[2], absx2(addx2(P2,  nm[2])));
    A[2] = addx2(A[2], absx2(addx2(P3,  nm[2])));
    B[2] = addx2(B[2], absx2(addx2(P32, nm[2])));

    A[4] = addx2(A[4], absx2(addx2(P2,  nm[4])));
    B[4] = addx2(B[4], absx2(addx2(P3,  nm[4])));
    A[4] = addx2(A[4], absx2(addx2(P32, nm[4])));
    B[4] = addx2(B[4], absx2(addx2(P33, nm[4])));

    A[6] = addx2(A[6], absx2(addx2(P3,  nm[6])));
    B[6] = addx2(B[6], absx2(addx2(P32, nm[6])));
    A[6] = addx2(A[6], absx2(addx2(P33, nm[6])));
    B[6] = addx2(B[6], absx2(addx2(P34, nm[6])));

    // Odd windows w=2a+1: full pairs a+1..a+31 + scalar ends e[w], f[w-1].
    A[1] = addx2(A[1], absx2(addx2(P1,  nm[1])));
    B[1] = addx2(B[1], absx2(addx2(P2,  nm[1])));
    A[1] = addx2(A[1], absx2(addx2(P3,  nm[1])));

    A[3] = addx2(A[3], absx2(addx2(P2,  nm[3])));
    B[3] = addx2(B[3], absx2(addx2(P3,  nm[3])));
    A[3] = addx2(A[3], absx2(addx2(P32, nm[3])));

    A[5] = addx2(A[5], absx2(addx2(P3,  nm[5])));
    B[5] = addx2(B[5], absx2(addx2(P32, nm[5])));
    A[5] = addx2(A[5], absx2(addx2(P33, nm[5])));

    A[7] = addx2(A[7], absx2(addx2(P32, nm[7])));
    B[7] = addx2(B[7], absx2(addx2(P33, nm[7])));
    A[7] = addx2(A[7], absx2(addx2(P34, nm[7])));

    const float ex1 = fabsf(e[1] - m[1]) + fabsf(f[0] - m[1]);
    const float ex3 = fabsf(e[3] - m[3]) + fabsf(f[2] - m[3]);
    const float ex5 = fabsf(e[5] - m[5]) + fabsf(f[4] - m[5]);
    const float ex7 = fabsf(e[7] - m[7]) + fabsf(f[6] - m[7]);

    a[0] = sum2(addx2(A[0], B[0]));
    a[1] = sum2(addx2(A[1], B[1])) + ex1;
    a[2] = sum2(addx2(A[2], B[2]));
    a[3] = sum2(addx2(A[3], B[3])) + ex3;
    a[4] = sum2(addx2(A[4], B[4]));
    a[5] = sum2(addx2(A[5], B[5])) + ex5;
    a[6] = sum2(addx2(A[6], B[6]));
    a[7] = sum2(addx2(A[7], B[7])) + ex7;
}

// Rare tail fallback (segment not fully in-bounds). Compact loops.
__device__ void seg8_scalar(const float* __restrict__ p, int rem, float a[WPT])
{
    #pragma unroll 1
    for (int w = 0; w < WPT; w++) {
        float s = 0.0f;
        #pragma unroll 1
        for (int j = 0; j < K_WIN; j++) {
            const int idx = w + j;
            s += (idx < rem) ? p[idx] : 0.0f;
        }
        const float m = s * (1.0f / (float)K_WIN);
        float t = 0.0f;
        #pragma unroll 1
        for (int j = 0; j < K_WIN; j++) {
            const int idx = w + j;
            const float x = (idx < rem) ? p[idx] : 0.0f;
            t += fabsf(x - m);
        }
        a[w] = t;
    }
}

__global__ void __launch_bounds__(BLOCK, 2)
smoothness_persist_kernel(const float* __restrict__ yh,
                          const float* __restrict__ yy,
                          int W, int N, int WB,
                          float* __restrict__ out, double invW)
{
    __shared__ float  redf[BLOCK / 32];
    __shared__ double redd[BLOCK / 32];
    __shared__ int    amLast;

    const int tid    = threadIdx.x;
    const int wstart = blockIdx.x * WB;            // multiple of 8
    const int wend   = min(wstart + WB, W);

    float d2 = 0.0f;

    #pragma unroll 1
    for (int i0 = wstart + WPT * tid; i0 < wend; i0 += STRIDE) {
        float a1[WPT], a2[WPT];
        if (N - i0 >= 8 * WPT + 8) {               // 72 elements fully in-bounds
            seg8(yh + i0, a1);
            seg8(yy + i0, a2);
        } else {
            seg8_scalar(yh + i0, N - i0, a1);
            seg8_scalar(yy + i0, N - i0, a2);
        }
        if (i0 + WPT <= wend) {
            #pragma unroll
            for (int w = 0; w < WPT; w++) {
                const float d = a1[w] - a2[w];
                d2 += d * d;
            }
        } else {
            #pragma unroll
            for (int w = 0; w < WPT; w++) {
                if (i0 + w < wend) {
                    const float d = a1[w] - a2[w];
                    d2 += d * d;
                }
            }
        }
    }

    // Block reduction of d2.
    #pragma unroll
    for (int off = 16; off > 0; off >>= 1)
        d2 += __shfl_down_sync(0xffffffffu, d2, off);

    const int lane = tid & 31, wid = tid >> 5;
    if (lane == 0) redf[wid] = d2;
    __syncthreads();
    if (wid == 0) {
        float vv = (lane < BLOCK / 32) ? redf[lane] : 0.0f;
        #pragma unroll
        for (int off = 4; off > 0; off >>= 1)
            vv += __shfl_down_sync(0xffffffffu, vv, off);
        if (lane == 0) {
            g_partials[blockIdx.x] = vv;
            __threadfence();
            unsigned int c = atomicAdd(&g_count, 1u);
            amLast = (c == (unsigned int)(gridDim.x - 1));
        }
    }
    __syncthreads();

    if (amLast) {
        // Deterministic final reduction (fixed order/topology).
        double s = 0.0;
        #pragma unroll 1
        for (int i = tid; i < GRID; i += BLOCK)
            s += (double)g_partials[i];
        #pragma unroll
        for (int off = 16; off > 0; off >>= 1)
            s += __shfl_down_sync(0xffffffffu, s, off);
        if (lane == 0) redd[wid] = s;
        __syncthreads();
        if (wid == 0) {
            double vv = (lane < BLOCK / 32) ? redd[lane] : 0.0;
            #pragma unroll
            for (int off = 4; off > 0; off >>= 1)
                vv += __shfl_down_sync(0xffffffffu, vv, off);
            if (lane == 0) {
                out[0] = (float)(vv * invW);
                g_count = 0;                 // reset for next graph replay
            }
        }
    }
}

extern "C" void kernel_launch(void* const* d_in, const int* in_sizes, int n_in,
                              void* d_out, int out_size)
{
    const float* yh = (const float*)d_in[0];
    const float* yy = (const float*)d_in[1];
    const int N = in_sizes[0];
    const int W = N - K_WIN - 1;
    int WB = (W + GRID - 1) / GRID;
    WB = (WB + 7) & ~7;                          // multiple of 8 (alignment + WPT)

    smoothness_persist_kernel<<<GRID, BLOCK>>>(yh, yy, W, N, WB,
                                               (float*)d_out, 1.0 / (double)W);
}